// round 14
// baseline (speedup 1.0000x reference)
#include <cuda_runtime.h>
#include <cuda_bf16.h>
#include <cuda_fp16.h>
#include <math.h>
#include <stdint.h>

#define N_NODES 100000
#define N_EDGES 1600000
#define F_IN    512
#define F_HID   64
#define F_OUT   40

#define CSR_GRID 592      // 4 blocks/SM x 148 SMs -> all co-resident
#define CSR_THR  256

// ---------------- scratch ----------------------------------------------------
__device__ int    g_deg_unused[1];
__device__ int    g_off[N_NODES + 1];
__device__ int    g_cur[N_NODES];
__device__ int    g_deg[N_NODES];
__device__ int    g_esrc[N_EDGES];
__device__ float  g_dinv[N_NODES];
__device__ __half g_h1[(size_t)N_NODES * F_HID];
__device__ __half g_h2[(size_t)N_NODES * F_OUT];
__device__ int    g_is64;
__device__ int    g_partials[CSR_GRID];
__device__ volatile unsigned g_bar;     // software grid barrier (reset by agg1)
__device__ __half g_w1t_hi[F_HID * F_IN];
__device__ __half g_w1t_lo[F_HID * F_IN];

#define W_SCALE   2048.0f
#define W_ISCALE  (1.0f / 2048.0f)

// ==================== helpers ====================
__device__ __forceinline__ uint32_t smem_u32(const void* p) {
    uint32_t a;
    asm("{ .reg .u64 t; cvta.to.shared.u64 t, %1; cvt.u32.u64 %0, t; }" : "=r"(a) : "l"(p));
    return a;
}
__device__ __forceinline__ uint32_t pack_h16(__half lo, __half hi) {
    return ((uint32_t)__half_as_ushort(hi) << 16) | (uint32_t)__half_as_ushort(lo);
}
__device__ __forceinline__ void ldmat_x4(uint32_t& r0, uint32_t& r1, uint32_t& r2, uint32_t& r3,
                                         uint32_t addr) {
    asm volatile("ldmatrix.sync.aligned.m8n8.x4.shared.b16 {%0,%1,%2,%3}, [%4];"
                 : "=r"(r0), "=r"(r1), "=r"(r2), "=r"(r3) : "r"(addr));
}
__device__ __forceinline__ void mma16816h(float* c, const uint32_t* a, const uint32_t* b) {
    asm volatile(
        "mma.sync.aligned.m16n8k16.row.col.f32.f16.f16.f32 "
        "{%0,%1,%2,%3}, {%4,%5,%6,%7}, {%8,%9}, {%0,%1,%2,%3};"
        : "+f"(c[0]), "+f"(c[1]), "+f"(c[2]), "+f"(c[3])
        : "r"(a[0]), "r"(a[1]), "r"(a[2]), "r"(a[3]), "r"(b[0]), "r"(b[1]));
}
__device__ __forceinline__ float2 h2_to_f2(uint32_t u) {
    __half2 h = *reinterpret_cast<__half2*>(&u);
    return __half22float2(h);
}
__device__ __forceinline__ int load_edge(const void* ei, long long idx, int is64) {
    if (is64) return (int)((const long long*)ei)[idx];
    return ((const int*)ei)[idx];
}

// ---------------- CSR build: single persistent kernel ----------------------
// 592 blocks x 256 threads, all co-resident (4/SM). Software grid barrier
// between phases. g_bar is reset by agg1_gemm2 (the next kernel) each run.
__global__ void __launch_bounds__(CSR_THR, 8) csr_build_kernel(const void* ei) {
    const int tid = threadIdx.x, b = blockIdx.x;
    const int gid = b * CSR_THR + tid;
    const int gsz = CSR_GRID * CSR_THR;       // 151552
    __shared__ int s[CSR_THR];

    unsigned gen = 0;
    #define GBAR()                                                         \
        do {                                                               \
            __syncthreads();                                               \
            if (tid == 0) {                                                \
                __threadfence();                                           \
                atomicAdd((unsigned*)&g_bar, 1u);                          \
                gen += CSR_GRID;                                           \
                while (g_bar < gen) { }                                    \
                __threadfence();                                           \
            }                                                              \
            __syncthreads();                                               \
        } while (0)

    // Phase A: zero degrees + dtype detect
    for (int i = gid; i < N_NODES; i += gsz) g_deg[i] = 0;
    if (gid == 0) {
        const int* e32 = (const int*)ei;
        g_is64 = (e32[1] == 0 && e32[3] == 0 && e32[5] == 0 && e32[7] == 0) ? 1 : 0;
    }
    GBAR();

    // Phase B: count in-degrees
    const int is64 = g_is64;
    for (int e = gid; e < N_EDGES; e += gsz) {
        int c = load_edge(ei, (long long)N_EDGES + e, is64);
        atomicAdd(&g_deg[c], 1);
    }
    GBAR();

    // Phase C: block-local inclusive scan (one node per thread; gsz >= N)
    int d = (gid < N_NODES) ? g_deg[gid] : 0;
    int val = d;
    s[tid] = val;
    __syncthreads();
    #pragma unroll
    for (int o = 1; o < CSR_THR; o <<= 1) {
        int t = (tid >= o) ? s[tid - o] : 0;
        __syncthreads();
        val += t;
        s[tid] = val;
        __syncthreads();
    }
    if (tid == CSR_THR - 1) g_partials[b] = val;
    GBAR();

    // Phase D: block 0 turns partials into exclusive block bases
    if (b == 0 && tid == 0) {
        int run = 0;
        for (int i = 0; i < CSR_GRID; i++) {
            int t = g_partials[i];
            g_partials[i] = run;
            run += t;
        }
        g_off[N_NODES] = run;
    }
    GBAR();

    // Phase E: write offsets / cur / dinv
    {
        int base = g_partials[b];
        if (gid < N_NODES) {
            int o = base + val - d;
            g_off[gid] = o;
            g_cur[gid] = o;
            g_dinv[gid] = rsqrtf((float)d + 1.0f);
        }
    }
    GBAR();

    // Phase F: scatter sources into CSR order
    for (int e = gid; e < N_EDGES; e += gsz) {
        int r = load_edge(ei, (long long)e, is64);
        int c = load_edge(ei, (long long)N_EDGES + e, is64);
        int p = atomicAdd(&g_cur[c], 1);
        g_esrc[p] = r;
    }
    #undef GBAR
}

// ---------------- W1 transpose + scale + fp16 hi/lo split -------------------
__global__ void prep_w1_kernel(const float* __restrict__ W1) {
    int idx = blockIdx.x * blockDim.x + threadIdx.x;
    if (idx >= F_HID * F_IN) return;
    int n = idx / F_IN, k = idx % F_IN;
    float v = W1[(size_t)k * F_HID + n] * W_SCALE;
    __half h = __float2half_rn(v);
    float lo = v - __half2float(h);
    g_w1t_hi[idx] = h;
    g_w1t_lo[idx] = __float2half_rn(lo);
}

// ---------------- GEMM1: h1 = x @ W1, fp16x2 (scaled), 512 threads ---------
#define ASTR   40
#define A_BUF  (128 * ASTR * 2)
#define B_BUF  (64 * ASTR * 2)
#define G1_SMEM (2 * A_BUF + 4 * B_BUF)

__global__ void __launch_bounds__(512, 2)
gemm1_mma_kernel(const float* __restrict__ x) {
    extern __shared__ char smem[];
    const uint32_t sb = smem_u32(smem);
    const uint32_t aB0  = sb;
    const uint32_t bHi0 = sb + 2 * A_BUF;
    const uint32_t bLo0 = sb + 2 * A_BUF + 2 * B_BUF;

    const int tid = threadIdx.x;
    const int lane = tid & 31;
    const int wid = tid >> 5;
    const int wm = wid >> 2;
    const int wn = wid & 3;
    const int bm = blockIdx.x * 128;

    const int ar = tid >> 2, aq = tid & 3;
    const bool arow_ok = (bm + ar) < N_NODES;
    const float4* __restrict__ asrc =
        reinterpret_cast<const float4*>(x + (size_t)(arow_ok ? bm + ar : 0) * F_IN);
    const int bidx = tid & 255;
    const int b_r = bidx >> 2, b_q = bidx & 3;
    const __half* __restrict__ bsrc = (tid < 256) ? g_w1t_hi : g_w1t_lo;
    const uint32_t bDst0 = ((tid < 256) ? bHi0 : bLo0) + (uint32_t)(b_r * ASTR + b_q * 8) * 2;

    #define A_CVT_STS(bufsel, PRE)                                               \
        do {                                                                      \
            const uint32_t off = (uint32_t)(bufsel) * A_BUF                       \
                               + (uint32_t)(ar * ASTR + aq * 8) * 2;              \
            uint32_t hv[4];                                                       \
            _Pragma("unroll")                                                     \
            for (int u = 0; u < 2; u++) {                                         \
                float4 v = PRE[u];                                                \
                hv[u * 2]     = pack_h16(__float2half_rn(v.x), __float2half_rn(v.y)); \
                hv[u * 2 + 1] = pack_h16(__float2half_rn(v.z), __float2half_rn(v.w)); \
            }                                                                     \
            asm volatile("st.shared.v4.b32 [%0], {%1,%2,%3,%4};" ::               \
                "r"(aB0 + off), "r"(hv[0]), "r"(hv[1]), "r"(hv[2]), "r"(hv[3]) : "memory"); \
        } while (0)

    float4 pre[2];
    {
        pre[0] = arow_ok ? asrc[aq * 2]     : make_float4(0.f, 0.f, 0.f, 0.f);
        pre[1] = arow_ok ? asrc[aq * 2 + 1] : make_float4(0.f, 0.f, 0.f, 0.f);
        uint4 bv = *reinterpret_cast<const uint4*>(&bsrc[(size_t)b_r * F_IN + b_q * 8]);
        asm volatile("st.shared.v4.b32 [%0], {%1,%2,%3,%4};" ::
            "r"(bDst0), "r"(bv.x), "r"(bv.y), "r"(bv.z), "r"(bv.w) : "memory");
        A_CVT_STS(0, pre);
    }
    __syncthreads();

    float acc[2][2][4];
    #pragma unroll
    for (int m = 0; m < 2; m++)
        #pragma unroll
        for (int n = 0; n < 2; n++)
            #pragma unroll
            for (int q = 0; q < 4; q++) acc[m][n][q] = 0.f;

    const int a_row = (lane & 15);
    const int a_kel = (lane >> 4) * 8;
    const int b_g   = lane >> 3;
    const int b_row = (b_g >> 1) * 8 + (lane & 7);
    const int b_kel = (b_g & 1) * 8;

    #pragma unroll 1
    for (int c = 0; c < 16; c++) {
        const int s = c & 1;
        uint4 bv;
        if (c < 15) {
            const int kc4 = (c + 1) * 8;
            pre[0] = arow_ok ? asrc[kc4 + aq * 2]     : make_float4(0.f, 0.f, 0.f, 0.f);
            pre[1] = arow_ok ? asrc[kc4 + aq * 2 + 1] : make_float4(0.f, 0.f, 0.f, 0.f);
            bv = *reinterpret_cast<const uint4*>(
                &bsrc[(size_t)b_r * F_IN + (c + 1) * 32 + b_q * 8]);
        }
        const uint32_t aOff = (uint32_t)s * A_BUF;
        const uint32_t bOff = (uint32_t)s * B_BUF;
        #pragma unroll
        for (int ks = 0; ks < 2; ks++) {
            uint32_t fA[2][4], fBh[2][2], fBl[2][2];
            #pragma unroll
            for (int mt = 0; mt < 2; mt++) {
                uint32_t off = aOff + (uint32_t)((wm * 32 + mt * 16 + a_row) * ASTR
                                                 + ks * 16 + a_kel) * 2;
                ldmat_x4(fA[mt][0], fA[mt][1], fA[mt][2], fA[mt][3], aB0 + off);
            }
            {
                uint32_t off = bOff + (uint32_t)((wn * 16 + b_row) * ASTR
                                                 + ks * 16 + b_kel) * 2;
                uint32_t r0, r1, r2, r3;
                ldmat_x4(r0, r1, r2, r3, bHi0 + off);
                fBh[0][0] = r0; fBh[0][1] = r1; fBh[1][0] = r2; fBh[1][1] = r3;
                ldmat_x4(r0, r1, r2, r3, bLo0 + off);
                fBl[0][0] = r0; fBl[0][1] = r1; fBl[1][0] = r2; fBl[1][1] = r3;
            }
            #pragma unroll
            for (int mt = 0; mt < 2; mt++)
                #pragma unroll
                for (int nt = 0; nt < 2; nt++) {
                    mma16816h(acc[mt][nt], fA[mt], fBh[nt]);
                    mma16816h(acc[mt][nt], fA[mt], fBl[nt]);
                }
        }
        if (c < 15) {
            asm volatile("st.shared.v4.b32 [%0], {%1,%2,%3,%4};" ::
                "r"(bDst0 + (uint32_t)(1 - s) * B_BUF),
                "r"(bv.x), "r"(bv.y), "r"(bv.z), "r"(bv.w) : "memory");
            A_CVT_STS(1 - s, pre);
        }
        __syncthreads();
    }

    #pragma unroll
    for (int mt = 0; mt < 2; mt++) {
        int r0 = bm + wm * 32 + mt * 16 + (lane >> 2);
        #pragma unroll
        for (int nt = 0; nt < 2; nt++) {
            int col = wn * 16 + nt * 8 + (lane & 3) * 2;
            if (r0 < N_NODES)
                *reinterpret_cast<__half2*>(&g_h1[(size_t)r0 * F_HID + col]) =
                    __floats2half2_rn(acc[mt][nt][0] * W_ISCALE, acc[mt][nt][1] * W_ISCALE);
            if (r0 + 8 < N_NODES)
                *reinterpret_cast<__half2*>(&g_h1[(size_t)(r0 + 8) * F_HID + col]) =
                    __floats2half2_rn(acc[mt][nt][2] * W_ISCALE, acc[mt][nt][3] * W_ISCALE);
        }
    }
    #undef A_CVT_STS
}

// ------- Fused: a1 = relu(agg(h1)+b1); h2' = (a1 @ W2) * dinv[v] -----------
__global__ __launch_bounds__(512) void agg1_gemm2_kernel(
    const float* __restrict__ b1, const float* __restrict__ W2)
{
    __shared__ float sa1[16][66];
    __shared__ float ws[64][40];
    const int tid = threadIdx.x;
    const int wid = tid >> 5;
    const int lane = tid & 31;
    const int v = blockIdx.x * 16 + wid;

    if (blockIdx.x == 0 && tid == 0) g_bar = 0;   // reset CSR grid barrier

    for (int i = tid; i < 64 * 40; i += 512) ws[i / 40][i % 40] = W2[i];

    if (v < N_NODES) {
        const int o0 = g_off[v], o1 = g_off[v + 1];
        const float dv = g_dinv[v];
        const uint32_t* __restrict__ h1u = reinterpret_cast<const uint32_t*>(g_h1);

        float axv[4] = {0.f, 0.f, 0.f, 0.f}, ayv[4] = {0.f, 0.f, 0.f, 0.f};
        #pragma unroll 1
        for (int base = o0; base < o1; base += 32) {
            const int m = min(32, o1 - base);
            int   e  = (lane < m) ? g_esrc[base + lane] : 0;
            float dd = (lane < m) ? g_dinv[e] : 0.f;
            int j = 0;
            #pragma unroll 1
            for (; j + 8 <= m; j += 8) {
                int si[8]; float di[8];
                #pragma unroll
                for (int q = 0; q < 8; q++) {
                    si[q] = __shfl_sync(0xffffffffu, e,  j + q);
                    di[q] = __shfl_sync(0xffffffffu, dd, j + q);
                }
                float2 vv[8];
                #pragma unroll
                for (int q = 0; q < 8; q++)
                    vv[q] = h2_to_f2(h1u[(size_t)si[q] * 32 + lane]);
                #pragma unroll
                for (int q = 0; q < 8; q++) {
                    axv[q & 3] = fmaf(vv[q].x, di[q], axv[q & 3]);
                    ayv[q & 3] = fmaf(vv[q].y, di[q], ayv[q & 3]);
                }
            }
            #pragma unroll 1
            for (; j < m; j++) {
                int   s0 = __shfl_sync(0xffffffffu, e,  j);
                float d0 = __shfl_sync(0xffffffffu, dd, j);
                float2 v0 = h2_to_f2(h1u[(size_t)s0 * 32 + lane]);
                axv[0] = fmaf(v0.x, d0, axv[0]); ayv[0] = fmaf(v0.y, d0, ayv[0]);
            }
        }
        float ax = (axv[0] + axv[1]) + (axv[2] + axv[3]);
        float ay = (ayv[0] + ayv[1]) + (ayv[2] + ayv[3]);
        float2 self = h2_to_f2(reinterpret_cast<const uint32_t*>(g_h1)[(size_t)v * 32 + lane]);
        float dd = dv * dv;
        float bx = b1[lane * 2], by = b1[lane * 2 + 1];
        sa1[wid][lane * 2]     = fmaxf(fmaf(ax, dv, fmaf(self.x, dd, bx)), 0.f);
        sa1[wid][lane * 2 + 1] = fmaxf(fmaf(ay, dv, fmaf(self.y, dd, by)), 0.f);
        if (lane == 0) sa1[wid][64] = dv;
    }
    __syncthreads();

    #pragma unroll
    for (int o = tid; o < 16 * F_OUT; o += 512) {
        int n = o / F_OUT, col = o % F_OUT;
        int gv = blockIdx.x * 16 + n;
        if (gv < N_NODES) {
            float acc = 0.f;
            #pragma unroll
            for (int k = 0; k < 64; k++)
                acc = fmaf(sa1[n][k], ws[k][col], acc);
            g_h2[(size_t)gv * F_OUT + col] = __float2half_rn(acc * sa1[n][64]);
        }
    }
}

// ----- Aggregation layer 2 + bias + log_softmax (h2 pre-scaled by dinv) ----
__global__ __launch_bounds__(256) void agg_lsm_kernel(
    const float* __restrict__ b2, float* __restrict__ out)
{
    const int v = (blockIdx.x * blockDim.x + threadIdx.x) >> 5;
    const int lane = threadIdx.x & 31;
    if (v >= N_NODES) return;
    const int o0 = g_off[v], o1 = g_off[v + 1];
    const float dv = g_dinv[v];
    const bool act = lane < 20;
    const int colidx = act ? lane : 0;
    const uint32_t* __restrict__ h2u = reinterpret_cast<const uint32_t*>(g_h2);

    float axv[4] = {0.f, 0.f, 0.f, 0.f}, ayv[4] = {0.f, 0.f, 0.f, 0.f};
    #pragma unroll 1
    for (int base = o0; base < o1; base += 32) {
        const int m = min(32, o1 - base);
        int e = (lane < m) ? g_esrc[base + lane] : 0;
        int j = 0;
        #pragma unroll 1
        for (; j + 4 <= m; j += 4) {
            int si[4];
            #pragma unroll
            for (int q = 0; q < 4; q++) si[q] = __shfl_sync(0xffffffffu, e, j + q);
            if (act) {
                float2 f0 = h2_to_f2(h2u[(size_t)si[0] * 20 + colidx]);
                float2 f1 = h2_to_f2(h2u[(size_t)si[1] * 20 + colidx]);
                float2 f2 = h2_to_f2(h2u[(size_t)si[2] * 20 + colidx]);
                float2 f3 = h2_to_f2(h2u[(size_t)si[3] * 20 + colidx]);
                axv[0] += f0.x; ayv[0] += f0.y;
                axv[1] += f1.x; ayv[1] += f1.y;
                axv[2] += f2.x; ayv[2] += f2.y;
                axv[3] += f3.x; ayv[3] += f3.y;
            }
        }
        #pragma unroll 1
        for (; j < m; j++) {
            int s0 = __shfl_sync(0xffffffffu, e, j);
            if (act) {
                float2 f0 = h2_to_f2(h2u[(size_t)s0 * 20 + colidx]);
                axv[0] += f0.x; ayv[0] += f0.y;
            }
        }
    }

    float val0 = __int_as_float(0xff800000), val1 = val0;
    if (act) {
        float2 self = h2_to_f2(h2u[(size_t)v * 20 + colidx]);
        float2 bb = reinterpret_cast<const float2*>(b2)[colidx];
        val0 = fmaf(dv, (axv[0] + axv[1]) + (axv[2] + axv[3]) + self.x, bb.x);
        val1 = fmaf(dv, (ayv[0] + ayv[1]) + (ayv[2] + ayv[3]) + self.y, bb.y);
    }

    float m = fmaxf(val0, val1);
    #pragma unroll
    for (int o = 16; o; o >>= 1) m = fmaxf(m, __shfl_xor_sync(0xffffffffu, m, o));
    float e = act ? (__expf(val0 - m) + __expf(val1 - m)) : 0.f;
    #pragma unroll
    for (int o = 16; o; o >>= 1) e += __shfl_xor_sync(0xffffffffu, e, o);
    float ls = logf(e);

    if (act)
        reinterpret_cast<float2*>(out)[(size_t)v * 20 + colidx] =
            make_float2(val0 - m - ls, val1 - m - ls);
}

// ---------------- launch ----------------------------------------------------
extern "C" void kernel_launch(void* const* d_in, const int* in_sizes, int n_in,
                              void* d_out, int out_size)
{
    const float* x  = (const float*)d_in[0];
    const void*  ei = d_in[1];
    const float* W1 = (const float*)d_in[2];
    const float* b1 = (const float*)d_in[3];
    const float* W2 = (const float*)d_in[4];
    const float* b2 = (const float*)d_in[5];
    float* out = (float*)d_out;

    cudaFuncSetAttribute(gemm1_mma_kernel,
                         cudaFuncAttributeMaxDynamicSharedMemorySize, G1_SMEM);

    const int WARP_BLOCKS = (N_NODES * 32 + 255) / 256;

    cudaStream_t s2;
    cudaStreamCreateWithFlags(&s2, cudaStreamNonBlocking);
    cudaEvent_t e0, eG;
    cudaEventCreateWithFlags(&e0, cudaEventDisableTiming);
    cudaEventCreateWithFlags(&eG, cudaEventDisableTiming);

    // Fork s2 off the capture stream, then:
    //   1: csr_build (stream 0)    2: prep_w1 (s2)    3: gemm1 (s2)
    //   4: agg1_gemm2 (stream 0)  <- profiled slot    5: agg_lsm
    cudaEventRecord(e0, 0);
    cudaStreamWaitEvent(s2, e0, 0);

    csr_build_kernel<<<CSR_GRID, CSR_THR>>>(ei);                        // 1
    prep_w1_kernel<<<(F_HID * F_IN + 255) / 256, 256, 0, s2>>>(W1);     // 2
    gemm1_mma_kernel<<<(N_NODES + 127) / 128, 512, G1_SMEM, s2>>>(x);   // 3
    cudaEventRecord(eG, s2);
    cudaStreamWaitEvent(0, eG, 0);

    agg1_gemm2_kernel<<<(N_NODES + 15) / 16, 512>>>(b1, W2);            // 4 <- profiled
    agg_lsm_kernel<<<WARP_BLOCKS, 256>>>(b2, out);                      // 5
}

// round 15
// speedup vs baseline: 1.3477x; 1.3477x over previous
#include <cuda_runtime.h>
#include <cuda_bf16.h>
#include <cuda_fp16.h>
#include <math.h>
#include <stdint.h>

#define N_NODES 100000
#define N_EDGES 1600000
#define F_IN    512
#define F_HID   64
#define F_OUT   40

// ---------------- scratch ----------------------------------------------------
__device__ int    g_deg[N_NODES];
__device__ int    g_off[N_NODES + 1];
__device__ int    g_cur[N_NODES];
__device__ uint2  g_epack[N_EDGES];      // per-edge {src*128 byte offset, dinv[src]}
__device__ float  g_dinv[N_NODES];
__device__ __half g_h1[(size_t)N_NODES * F_HID];       // 128 B/row
__device__ __half g_h2[(size_t)N_NODES * F_HID];       // padded to 128 B/row (40 used)
__device__ int    g_is64;
__device__ int    g_spart[128];
__device__ volatile int g_sflag[128];
__device__ __half g_w1t_hi[F_HID * F_IN];
__device__ __half g_w1t_lo[F_HID * F_IN];

#define W_SCALE   2048.0f
#define W_ISCALE  (1.0f / 2048.0f)

// ==================== helpers ====================
__device__ __forceinline__ uint32_t smem_u32(const void* p) {
    uint32_t a;
    asm("{ .reg .u64 t; cvta.to.shared.u64 t, %1; cvt.u32.u64 %0, t; }" : "=r"(a) : "l"(p));
    return a;
}
__device__ __forceinline__ uint32_t pack_h16(__half lo, __half hi) {
    return ((uint32_t)__half_as_ushort(hi) << 16) | (uint32_t)__half_as_ushort(lo);
}
__device__ __forceinline__ void ldmat_x4(uint32_t& r0, uint32_t& r1, uint32_t& r2, uint32_t& r3,
                                         uint32_t addr) {
    asm volatile("ldmatrix.sync.aligned.m8n8.x4.shared.b16 {%0,%1,%2,%3}, [%4];"
                 : "=r"(r0), "=r"(r1), "=r"(r2), "=r"(r3) : "r"(addr));
}
__device__ __forceinline__ void mma16816h(float* c, const uint32_t* a, const uint32_t* b) {
    asm volatile(
        "mma.sync.aligned.m16n8k16.row.col.f32.f16.f16.f32 "
        "{%0,%1,%2,%3}, {%4,%5,%6,%7}, {%8,%9}, {%0,%1,%2,%3};"
        : "+f"(c[0]), "+f"(c[1]), "+f"(c[2]), "+f"(c[3])
        : "r"(a[0]), "r"(a[1]), "r"(a[2]), "r"(a[3]), "r"(b[0]), "r"(b[1]));
}
__device__ __forceinline__ float2 h2_to_f2(uint32_t u) {
    __half2 h = *reinterpret_cast<__half2*>(&u);
    return __half22float2(h);
}
__device__ __forceinline__ int load_edge(const void* ei, long long idx, int is64) {
    if (is64) return (int)((const long long*)ei)[idx];
    return ((const int*)ei)[idx];
}

// ---------------- CSR build (multi-kernel, R12-proven) ----------------------
__global__ void zero_detect_kernel(const int* ei32) {
    int i = blockIdx.x * blockDim.x + threadIdx.x;
    if (i < N_NODES) g_deg[i] = 0;
    if (i < 128) g_sflag[i] = 0;
    if (i == 0) {
        bool is64 = (ei32[1] == 0 && ei32[3] == 0 && ei32[5] == 0 && ei32[7] == 0);
        g_is64 = is64 ? 1 : 0;
    }
}
__global__ void count_kernel(const void* ei) {
    int e = blockIdx.x * blockDim.x + threadIdx.x;
    if (e >= N_EDGES) return;
    int c = load_edge(ei, (long long)N_EDGES + e, g_is64);
    atomicAdd(&g_deg[c], 1);
}
// Single-pass scan with decoupled lookback (block b waits only on p < b).
__global__ __launch_bounds__(1024) void scan_fused_kernel(int nblocks) {
    __shared__ int s[1024];
    __shared__ int wsum[32];
    __shared__ int sbase;
    const int b = blockIdx.x, tid = threadIdx.x;
    const int lane = tid & 31, wid = tid >> 5;
    const int i = b * 1024 + tid;
    int d = (i < N_NODES) ? g_deg[i] : 0;
    int val = d;
    s[tid] = val;
    __syncthreads();
    #pragma unroll
    for (int o = 1; o < 1024; o <<= 1) {
        int t = (tid >= o) ? s[tid - o] : 0;
        __syncthreads();
        val += t;
        s[tid] = val;
        __syncthreads();
    }
    if (tid == 1023) {
        g_spart[b] = val;
        __threadfence();
        g_sflag[b] = 1;
    }
    int contrib = 0;
    for (int p = tid; p < b; p += 1024) {
        while (g_sflag[p] == 0) { }
        contrib += g_spart[p];
    }
    #pragma unroll
    for (int o = 16; o; o >>= 1) contrib += __shfl_xor_sync(0xffffffffu, contrib, o);
    if (lane == 0) wsum[wid] = contrib;
    __syncthreads();
    if (tid < 32) {
        int vsum = wsum[tid];
        #pragma unroll
        for (int o = 16; o; o >>= 1) vsum += __shfl_xor_sync(0xffffffffu, vsum, o);
        if (tid == 0) sbase = vsum;
    }
    __syncthreads();
    const int base = sbase;
    if (i < N_NODES) {
        int o = base + val - d;
        g_off[i] = o;
        g_cur[i] = o;
        g_dinv[i] = rsqrtf((float)d + 1.0f);
    }
    if (b == nblocks - 1 && tid == 1023) g_off[N_NODES] = base + val;
}
// Scatter: write packed {src*128, dinv[src]} per edge in CSR order.
__global__ void scatter_pack_kernel(const void* ei) {
    int e = blockIdx.x * blockDim.x + threadIdx.x;
    if (e >= N_EDGES) return;
    int is64 = g_is64;
    int r = load_edge(ei, (long long)e, is64);
    int c = load_edge(ei, (long long)N_EDGES + e, is64);
    int p = atomicAdd(&g_cur[c], 1);
    g_epack[p] = make_uint2((uint32_t)r << 7, __float_as_uint(g_dinv[r]));
}

// ---------------- W1 transpose + scale + fp16 hi/lo split -------------------
__global__ void prep_w1_kernel(const float* __restrict__ W1) {
    int idx = blockIdx.x * blockDim.x + threadIdx.x;
    if (idx >= F_HID * F_IN) return;
    int n = idx / F_IN, k = idx % F_IN;
    float v = W1[(size_t)k * F_HID + n] * W_SCALE;
    __half h = __float2half_rn(v);
    float lo = v - __half2float(h);
    g_w1t_hi[idx] = h;
    g_w1t_lo[idx] = __float2half_rn(lo);
}

// ---------------- GEMM1: h1 = x @ W1, fp16x2 (scaled), 512 threads ---------
#define ASTR   40
#define A_BUF  (128 * ASTR * 2)
#define B_BUF  (64 * ASTR * 2)
#define G1_SMEM (2 * A_BUF + 4 * B_BUF)

__global__ void __launch_bounds__(512, 2)
gemm1_mma_kernel(const float* __restrict__ x) {
    extern __shared__ char smem[];
    const uint32_t sb = smem_u32(smem);
    const uint32_t aB0  = sb;
    const uint32_t bHi0 = sb + 2 * A_BUF;
    const uint32_t bLo0 = sb + 2 * A_BUF + 2 * B_BUF;

    const int tid = threadIdx.x;
    const int lane = tid & 31;
    const int wid = tid >> 5;
    const int wm = wid >> 2;
    const int wn = wid & 3;
    const int bm = blockIdx.x * 128;

    const int ar = tid >> 2, aq = tid & 3;
    const bool arow_ok = (bm + ar) < N_NODES;
    const float4* __restrict__ asrc =
        reinterpret_cast<const float4*>(x + (size_t)(arow_ok ? bm + ar : 0) * F_IN);
    const int bidx = tid & 255;
    const int b_r = bidx >> 2, b_q = bidx & 3;
    const __half* __restrict__ bsrc = (tid < 256) ? g_w1t_hi : g_w1t_lo;
    const uint32_t bDst0 = ((tid < 256) ? bHi0 : bLo0) + (uint32_t)(b_r * ASTR + b_q * 8) * 2;

    #define A_CVT_STS(bufsel, PRE)                                               \
        do {                                                                      \
            const uint32_t off = (uint32_t)(bufsel) * A_BUF                       \
                               + (uint32_t)(ar * ASTR + aq * 8) * 2;              \
            uint32_t hv[4];                                                       \
            _Pragma("unroll")                                                     \
            for (int u = 0; u < 2; u++) {                                         \
                float4 v = PRE[u];                                                \
                hv[u * 2]     = pack_h16(__float2half_rn(v.x), __float2half_rn(v.y)); \
                hv[u * 2 + 1] = pack_h16(__float2half_rn(v.z), __float2half_rn(v.w)); \
            }                                                                     \
            asm volatile("st.shared.v4.b32 [%0], {%1,%2,%3,%4};" ::               \
                "r"(aB0 + off), "r"(hv[0]), "r"(hv[1]), "r"(hv[2]), "r"(hv[3]) : "memory"); \
        } while (0)

    float4 pre[2];
    {
        pre[0] = arow_ok ? asrc[aq * 2]     : make_float4(0.f, 0.f, 0.f, 0.f);
        pre[1] = arow_ok ? asrc[aq * 2 + 1] : make_float4(0.f, 0.f, 0.f, 0.f);
        uint4 bv = *reinterpret_cast<const uint4*>(&bsrc[(size_t)b_r * F_IN + b_q * 8]);
        asm volatile("st.shared.v4.b32 [%0], {%1,%2,%3,%4};" ::
            "r"(bDst0), "r"(bv.x), "r"(bv.y), "r"(bv.z), "r"(bv.w) : "memory");
        A_CVT_STS(0, pre);
    }
    __syncthreads();

    float acc[2][2][4];
    #pragma unroll
    for (int m = 0; m < 2; m++)
        #pragma unroll
        for (int n = 0; n < 2; n++)
            #pragma unroll
            for (int q = 0; q < 4; q++) acc[m][n][q] = 0.f;

    const int a_row = (lane & 15);
    const int a_kel = (lane >> 4) * 8;
    const int b_g   = lane >> 3;
    const int b_row = (b_g >> 1) * 8 + (lane & 7);
    const int b_kel = (b_g & 1) * 8;

    #pragma unroll 1
    for (int c = 0; c < 16; c++) {
        const int s = c & 1;
        uint4 bv;
        if (c < 15) {
            const int kc4 = (c + 1) * 8;
            pre[0] = arow_ok ? asrc[kc4 + aq * 2]     : make_float4(0.f, 0.f, 0.f, 0.f);
            pre[1] = arow_ok ? asrc[kc4 + aq * 2 + 1] : make_float4(0.f, 0.f, 0.f, 0.f);
            bv = *reinterpret_cast<const uint4*>(
                &bsrc[(size_t)b_r * F_IN + (c + 1) * 32 + b_q * 8]);
        }
        const uint32_t aOff = (uint32_t)s * A_BUF;
        const uint32_t bOff = (uint32_t)s * B_BUF;
        #pragma unroll
        for (int ks = 0; ks < 2; ks++) {
            uint32_t fA[2][4], fBh[2][2], fBl[2][2];
            #pragma unroll
            for (int mt = 0; mt < 2; mt++) {
                uint32_t off = aOff + (uint32_t)((wm * 32 + mt * 16 + a_row) * ASTR
                                                 + ks * 16 + a_kel) * 2;
                ldmat_x4(fA[mt][0], fA[mt][1], fA[mt][2], fA[mt][3], aB0 + off);
            }
            {
                uint32_t off = bOff + (uint32_t)((wn * 16 + b_row) * ASTR
                                                 + ks * 16 + b_kel) * 2;
                uint32_t r0, r1, r2, r3;
                ldmat_x4(r0, r1, r2, r3, bHi0 + off);
                fBh[0][0] = r0; fBh[0][1] = r1; fBh[1][0] = r2; fBh[1][1] = r3;
                ldmat_x4(r0, r1, r2, r3, bLo0 + off);
                fBl[0][0] = r0; fBl[0][1] = r1; fBl[1][0] = r2; fBl[1][1] = r3;
            }
            #pragma unroll
            for (int mt = 0; mt < 2; mt++)
                #pragma unroll
                for (int nt = 0; nt < 2; nt++) {
                    mma16816h(acc[mt][nt], fA[mt], fBh[nt]);
                    mma16816h(acc[mt][nt], fA[mt], fBl[nt]);
                }
        }
        if (c < 15) {
            asm volatile("st.shared.v4.b32 [%0], {%1,%2,%3,%4};" ::
                "r"(bDst0 + (uint32_t)(1 - s) * B_BUF),
                "r"(bv.x), "r"(bv.y), "r"(bv.z), "r"(bv.w) : "memory");
            A_CVT_STS(1 - s, pre);
        }
        __syncthreads();
    }

    #pragma unroll
    for (int mt = 0; mt < 2; mt++) {
        int r0 = bm + wm * 32 + mt * 16 + (lane >> 2);
        #pragma unroll
        for (int nt = 0; nt < 2; nt++) {
            int col = wn * 16 + nt * 8 + (lane & 3) * 2;
            if (r0 < N_NODES)
                *reinterpret_cast<__half2*>(&g_h1[(size_t)r0 * F_HID + col]) =
                    __floats2half2_rn(acc[mt][nt][0] * W_ISCALE, acc[mt][nt][1] * W_ISCALE);
            if (r0 + 8 < N_NODES)
                *reinterpret_cast<__half2*>(&g_h1[(size_t)(r0 + 8) * F_HID + col]) =
                    __floats2half2_rn(acc[mt][nt][2] * W_ISCALE, acc[mt][nt][3] * W_ISCALE);
        }
    }
    #undef A_CVT_STS
}

// ------- Fused: a1 = relu(agg(h1)+b1); h2' = (a1 @ W2) * dinv[v] -----------
// Per-edge work: 1 uniform LDG.64 (epack) + 1 lane LDG.32 (h1) + 2 cvt + 2 FMA.
__global__ __launch_bounds__(512) void agg1_gemm2_kernel(
    const float* __restrict__ b1, const float* __restrict__ W2)
{
    __shared__ float sa1[16][66];
    __shared__ float ws[64][40];
    const int tid = threadIdx.x;
    const int wid = tid >> 5;
    const int lane = tid & 31;
    const int v = blockIdx.x * 16 + wid;

    for (int i = tid; i < 64 * 40; i += 512) ws[i / 40][i % 40] = W2[i];

    if (v < N_NODES) {
        const int o0 = g_off[v], o1 = g_off[v + 1];
        const float dv = g_dinv[v];
        const char* __restrict__ h1b = reinterpret_cast<const char*>(g_h1);
        const uint2* __restrict__ ep = g_epack;
        const uint32_t l4 = (uint32_t)lane * 4;

        float ax0 = 0.f, ay0 = 0.f, ax1 = 0.f, ay1 = 0.f;
        float ax2 = 0.f, ay2 = 0.f, ax3 = 0.f, ay3 = 0.f;
        int j = o0;
        #pragma unroll 1
        for (; j + 4 <= o1; j += 4) {
            uint2 p0 = ep[j], p1 = ep[j + 1], p2 = ep[j + 2], p3 = ep[j + 3];
            float2 v0 = h2_to_f2(*reinterpret_cast<const uint32_t*>(h1b + p0.x + l4));
            float2 v1 = h2_to_f2(*reinterpret_cast<const uint32_t*>(h1b + p1.x + l4));
            float2 v2 = h2_to_f2(*reinterpret_cast<const uint32_t*>(h1b + p2.x + l4));
            float2 v3 = h2_to_f2(*reinterpret_cast<const uint32_t*>(h1b + p3.x + l4));
            float d0 = __uint_as_float(p0.y), d1 = __uint_as_float(p1.y);
            float d2 = __uint_as_float(p2.y), d3 = __uint_as_float(p3.y);
            ax0 = fmaf(v0.x, d0, ax0); ay0 = fmaf(v0.y, d0, ay0);
            ax1 = fmaf(v1.x, d1, ax1); ay1 = fmaf(v1.y, d1, ay1);
            ax2 = fmaf(v2.x, d2, ax2); ay2 = fmaf(v2.y, d2, ay2);
            ax3 = fmaf(v3.x, d3, ax3); ay3 = fmaf(v3.y, d3, ay3);
        }
        #pragma unroll 1
        for (; j < o1; j++) {
            uint2 p0 = ep[j];
            float2 v0 = h2_to_f2(*reinterpret_cast<const uint32_t*>(h1b + p0.x + l4));
            float d0 = __uint_as_float(p0.y);
            ax0 = fmaf(v0.x, d0, ax0); ay0 = fmaf(v0.y, d0, ay0);
        }
        float ax = (ax0 + ax1) + (ax2 + ax3);
        float ay = (ay0 + ay1) + (ay2 + ay3);
        float2 self = h2_to_f2(*reinterpret_cast<const uint32_t*>(
            h1b + ((uint32_t)v << 7) + l4));
        float dd = dv * dv;
        float bx = b1[lane * 2], by = b1[lane * 2 + 1];
        sa1[wid][lane * 2]     = fmaxf(fmaf(ax, dv, fmaf(self.x, dd, bx)), 0.f);
        sa1[wid][lane * 2 + 1] = fmaxf(fmaf(ay, dv, fmaf(self.y, dd, by)), 0.f);
        if (lane == 0) sa1[wid][64] = dv;
    }
    __syncthreads();

    #pragma unroll
    for (int o = tid; o < 16 * F_OUT; o += 512) {
        int n = o / F_OUT, col = o % F_OUT;
        int gv = blockIdx.x * 16 + n;
        if (gv < N_NODES) {
            float acc = 0.f;
            #pragma unroll
            for (int k = 0; k < 64; k++)
                acc = fmaf(sa1[n][k], ws[k][col], acc);
            // h2 padded to 64 halves/row so the 128B epack offsets also index it
            g_h2[(size_t)gv * F_HID + col] = __float2half_rn(acc * sa1[n][64]);
        }
    }
}

// ----- Aggregation layer 2 + bias + log_softmax (h2 pre-scaled, padded) ----
__global__ __launch_bounds__(256) void agg_lsm_kernel(
    const float* __restrict__ b2, float* __restrict__ out)
{
    const int v = (blockIdx.x * blockDim.x + threadIdx.x) >> 5;
    const int lane = threadIdx.x & 31;
    if (v >= N_NODES) return;
    const int o0 = g_off[v], o1 = g_off[v + 1];
    const float dv = g_dinv[v];
    const bool act = lane < 20;
    const uint32_t l4 = act ? (uint32_t)lane * 4 : 0;
    const char* __restrict__ h2b = reinterpret_cast<const char*>(g_h2);
    const uint2* __restrict__ ep = g_epack;

    float ax0 = 0.f, ay0 = 0.f, ax1 = 0.f, ay1 = 0.f;
    float ax2 = 0.f, ay2 = 0.f, ax3 = 0.f, ay3 = 0.f;
    int j = o0;
    #pragma unroll 1
    for (; j + 4 <= o1; j += 4) {
        uint32_t p0 = ep[j].x, p1 = ep[j + 1].x, p2 = ep[j + 2].x, p3 = ep[j + 3].x;
        if (act) {
            float2 f0 = h2_to_f2(*reinterpret_cast<const uint32_t*>(h2b + p0 + l4));
            float2 f1 = h2_to_f2(*reinterpret_cast<const uint32_t*>(h2b + p1 + l4));
            float2 f2 = h2_to_f2(*reinterpret_cast<const uint32_t*>(h2b + p2 + l4));
            float2 f3 = h2_to_f2(*reinterpret_cast<const uint32_t*>(h2b + p3 + l4));
            ax0 += f0.x; ay0 += f0.y;
            ax1 += f1.x; ay1 += f1.y;
            ax2 += f2.x; ay2 += f2.y;
            ax3 += f3.x; ay3 += f3.y;
        }
    }
    #pragma unroll 1
    for (; j < o1; j++) {
        uint32_t p0 = ep[j].x;
        if (act) {
            float2 f0 = h2_to_f2(*reinterpret_cast<const uint32_t*>(h2b + p0 + l4));
            ax0 += f0.x; ay0 += f0.y;
        }
    }

    float val0 = __int_as_float(0xff800000), val1 = val0;
    if (act) {
        float2 self = h2_to_f2(*reinterpret_cast<const uint32_t*>(
            h2b + ((uint32_t)v << 7) + l4));
        float2 bb = reinterpret_cast<const float2*>(b2)[lane];
        val0 = fmaf(dv, (ax0 + ax1) + (ax2 + ax3) + self.x, bb.x);
        val1 = fmaf(dv, (ay0 + ay1) + (ay2 + ay3) + self.y, bb.y);
    }

    float m = fmaxf(val0, val1);
    #pragma unroll
    for (int o = 16; o; o >>= 1) m = fmaxf(m, __shfl_xor_sync(0xffffffffu, m, o));
    float e = act ? (__expf(val0 - m) + __expf(val1 - m)) : 0.f;
    #pragma unroll
    for (int o = 16; o; o >>= 1) e += __shfl_xor_sync(0xffffffffu, e, o);
    float ls = logf(e);

    if (act)
        reinterpret_cast<float2*>(out)[(size_t)v * 20 + lane] =
            make_float2(val0 - m - ls, val1 - m - ls);
}

// ---------------- launch ----------------------------------------------------
extern "C" void kernel_launch(void* const* d_in, const int* in_sizes, int n_in,
                              void* d_out, int out_size)
{
    const float* x  = (const float*)d_in[0];
    const void*  ei = d_in[1];
    const float* W1 = (const float*)d_in[2];
    const float* b1 = (const float*)d_in[3];
    const float* W2 = (const float*)d_in[4];
    const float* b2 = (const float*)d_in[5];
    float* out = (float*)d_out;

    cudaFuncSetAttribute(gemm1_mma_kernel,
                         cudaFuncAttributeMaxDynamicSharedMemorySize, G1_SMEM);

    const int SCAN_BLOCKS = (N_NODES + 1023) / 1024;  // 98
    const int WARP_BLOCKS = (N_NODES * 32 + 255) / 256;

    cudaStream_t s2;
    cudaStreamCreateWithFlags(&s2, cudaStreamNonBlocking);
    cudaEvent_t e0, eG;
    cudaEventCreateWithFlags(&e0, cudaEventDisableTiming);
    cudaEventCreateWithFlags(&eG, cudaEventDisableTiming);

    cudaEventRecord(e0, 0);
    cudaStreamWaitEvent(s2, e0, 0);

    // CSR chain on stream 0; gemm1 chain concurrent on s2.
    zero_detect_kernel<<<(N_NODES + 255) / 256, 256>>>((const int*)ei);  // 1
    count_kernel<<<(N_EDGES + 255) / 256, 256>>>(ei);                    // 2
    scan_fused_kernel<<<SCAN_BLOCKS, 1024>>>(SCAN_BLOCKS);               // 3
    scatter_pack_kernel<<<(N_EDGES + 255) / 256, 256>>>(ei);             // 4 <- profiled

    prep_w1_kernel<<<(F_HID * F_IN + 255) / 256, 256, 0, s2>>>(W1);      // 5
    gemm1_mma_kernel<<<(N_NODES + 127) / 128, 512, G1_SMEM, s2>>>(x);    // 6
    cudaEventRecord(eG, s2);
    cudaStreamWaitEvent(0, eG, 0);

    agg1_gemm2_kernel<<<(N_NODES + 15) / 16, 512>>>(b1, W2);             // 7
    agg_lsm_kernel<<<WARP_BLOCKS, 256>>>(b2, out);                       // 8
}